// round 17
// baseline (speedup 1.0000x reference)
#include <cuda_runtime.h>
#include <cstdint>

#define ROWS        8192
#define COLS        32768
#define K_TOP       32
#define PRE_THRESH  2.8f

#define NTH         512
#define VEC         8                       // floats per access (256-bit)
#define ITERS       (COLS / VEC / NTH)      // 8 v8-accesses per thread
#define BATCH       2                       // front-batched v8 loads per group
#define GROUPS      (ITERS / BATCH)         // 4
#define CAND_CAP    192                     // mean ~84, sigma ~9.1 -> 11.8 sigma

#define NSM         148
#define CTAS_PER_SM 4
#define GRID        (NSM * CTAS_PER_SM)     // 592 persistent CTAs

__device__ __forceinline__ unsigned fmap(float f) {
    unsigned b = __float_as_uint(f);
    return (b & 0x80000000u) ? ~b : (b | 0x80000000u);
}
__device__ __forceinline__ float unfmap(unsigned u) {
    unsigned b = (u & 0x80000000u) ? (u ^ 0x80000000u) : ~u;
    return __uint_as_float(b);
}
// unique key: value desc, index asc tiebreak (matches jax.lax.top_k)
__device__ __forceinline__ unsigned long long make_key(float v, int idx) {
    return ((unsigned long long)fmap(v) << 32) | (unsigned)(~idx);
}

// 256-bit streaming global load/store (sm_100+)
__device__ __forceinline__ void ldg8_cs(const float* p, float* v) {
    asm volatile("ld.global.cs.v8.f32 {%0,%1,%2,%3,%4,%5,%6,%7}, [%8];"
                 : "=f"(v[0]), "=f"(v[1]), "=f"(v[2]), "=f"(v[3]),
                   "=f"(v[4]), "=f"(v[5]), "=f"(v[6]), "=f"(v[7])
                 : "l"(p));
}
__device__ __forceinline__ void stg8_cs_zero(float* p) {
    asm volatile("st.global.cs.v8.f32 [%0], {%1,%1,%1,%1,%1,%1,%1,%1};"
                 :: "l"(p), "f"(0.0f) : "memory");
}

// warp-aggregated histogram add (fallback path only)
__device__ __forceinline__ void hist_add(int* hist, int digit) {
    const unsigned act   = __activemask();
    const unsigned peers = __match_any_sync(act, digit);
    const int      lane  = threadIdx.x & 31;
    if ((__ffs(peers) - 1) == lane)
        atomicAdd(&hist[digit], __popc(peers));
}

// ---------------------------------------------------------------------------
// Persistent kernel: 592 CTAs, each grid-strides over ~14 rows. Per row:
// v8 read + zero-store stream with smem candidate gather, then the inline
// ~500-cycle rank-select + scatter. No wave transitions, prologue once.
// ---------------------------------------------------------------------------
__global__ __launch_bounds__(NTH) void topk_kernel(
    const float* __restrict__ x, float* __restrict__ out)
{
    __shared__ __align__(16) unsigned long long s_keys[CAND_CAP + 2];
    __shared__ int s_cnt;
    __shared__ int s_hist[256];
    __shared__ int s_digit, s_want, s_bcnt;

    const int tid = threadIdx.x;

    for (int row = blockIdx.x; row < ROWS; row += GRID) {
        const size_t row_off = (size_t)row * COLS;

        if (tid == 0) s_cnt = 0;
        __syncthreads();

        const float* __restrict__ xin = x + row_off;
        float* __restrict__       zo  = out + row_off;

        // --------- Phase 1: stream (front-batched v8 groups) --------------
        #pragma unroll
        for (int g = 0; g < GROUPS; g++) {
            float v[BATCH][VEC];
            #pragma unroll
            for (int k = 0; k < BATCH; k++)
                ldg8_cs(xin + (tid + (g * BATCH + k) * NTH) * VEC, v[k]);
            #pragma unroll
            for (int k = 0; k < BATCH; k++)
                stg8_cs_zero(zo + (tid + (g * BATCH + k) * NTH) * VEC);
            #pragma unroll
            for (int k = 0; k < BATCH; k++) {
                const int gidx = (tid + (g * BATCH + k) * NTH) * VEC;
                #pragma unroll
                for (int e = 0; e < VEC; e++) {
                    if (v[k][e] >= PRE_THRESH) {
                        int p = atomicAdd(&s_cnt, 1);
                        if (p < CAND_CAP) s_keys[p] = make_key(v[k][e], gidx + e);
                    }
                }
            }
        }
        __syncthreads();

        const int cnt = s_cnt;
        // zero-pad odd slot so the LDS.128 pair loop is exact (0 < any key)
        if (tid == 0 && (cnt & 1) && cnt < CAND_CAP) s_keys[cnt] = 0;
        __syncthreads();

        const bool fast = (cnt >= K_TOP) && (cnt <= CAND_CAP);

        if (fast) {
            // --------- Phase 2: rank-select over unique keys (inline) -----
            if (tid < cnt) {
                const unsigned long long k0 = s_keys[tid];
                const ulonglong2* __restrict__ kv =
                    reinterpret_cast<const ulonglong2*>(s_keys);
                const int nh = (cnt + 1) >> 1;
                int r0 = 0;
                #pragma unroll 4
                for (int j = 0; j < nh; j++) {
                    const ulonglong2 p = kv[j];      // LDS.128 broadcast
                    r0 += (int)(p.x > k0) + (int)(p.y > k0);
                }
                if (r0 < K_TOP) {
                    const int idx = (int)(~(unsigned)k0) & (COLS - 1);
                    out[row_off + idx] = fmaxf(unfmap((unsigned)(k0 >> 32)), 0.f);
                }
            }
        } else {
            // --------- Fallback: in-block full-row radix (exact) ----------
            unsigned long long prefix = 0, T = 0;
            int want = K_TOP;
            for (int shift = 56; shift >= 0; shift -= 8) {
                if (tid < 256) s_hist[tid] = 0;
                __syncthreads();
                for (int j = tid; j < COLS; j += NTH) {
                    unsigned long long key = make_key(x[row_off + j], j);
                    if (shift == 56 || (key >> (shift + 8)) == prefix)
                        hist_add(s_hist, (int)((key >> shift) & 255));
                }
                __syncthreads();
                if (tid == 0) {
                    int acc = 0, d = 255;
                    for (; d >= 0; d--) {
                        if (acc + s_hist[d] >= want) break;
                        acc += s_hist[d];
                    }
                    if (d < 0) d = 0;
                    s_digit = d; s_want = want - acc; s_bcnt = s_hist[d];
                }
                __syncthreads();
                prefix = (prefix << 8) | (unsigned long long)s_digit;
                want   = s_want;
                const int c = s_bcnt;
                if (want == c) { T = prefix << shift; break; }
                __syncthreads();
                // unique keys -> break always fires by shift==0
            }
            for (int j = tid; j < COLS; j += NTH) {
                unsigned long long key = make_key(x[row_off + j], j);
                if (key >= T) {
                    const int idx = (int)(~(unsigned)key) & (COLS - 1);
                    out[row_off + idx] = fmaxf(unfmap((unsigned)(key >> 32)), 0.f);
                }
            }
        }
        __syncthreads();   // s_cnt/s_keys reuse safe before next row
    }
}

extern "C" void kernel_launch(void* const* d_in, const int* in_sizes, int n_in,
                              void* d_out, int out_size)
{
    const float* x = (const float*)d_in[0];
    float* out = (float*)d_out;
    topk_kernel<<<GRID, NTH>>>(x, out);
}